// round 16
// baseline (speedup 1.0000x reference)
#include <cuda_runtime.h>
#include <cuda_fp16.h>
#include <cstdint>
#include <math.h>

#define NB 16
#define NC 64
#define IMG 256
#define PLANE 65536

// scratch (device globals — no allocation allowed)
__device__ float g_y[NB * 64 * NC];                 // [b][n][c] pooled tokens
__device__ unsigned long long g_xpack[16777216];    // x fp16: [bc][ig][nh][k=64][px=128] (134MB)
__device__ __align__(16) unsigned char g_Apack[NB * 9216]; // dist fp16, 64 rows x 144B

// dependency flags (zero-init; self-reset per batch each run)
__device__ unsigned g_pool_done[NB];
__device__ unsigned g_dist_done[NB];
__device__ unsigned g_att_done[NB];

#define N_ITEMS 5136   // 64 pool(b0) + 15*(64 pool + 1 dist + 256 att) + (1 dist + 256 att)
#define SMEM_FUSED 49152

__device__ __forceinline__ uint32_t smem_u32(const void* p) {
    uint32_t a;
    asm("{ .reg .u64 t; cvta.to.shared.u64 t, %1; cvt.u32.u64 %0, t; }"
        : "=r"(a) : "l"(p));
    return a;
}

__device__ __forceinline__ void wait_flag(unsigned* f, unsigned target) {
    if (threadIdx.x == 0) {
        while (atomicAdd(f, 0u) < target) __nanosleep(128);
        __threadfence();
    }
    __syncthreads();
}

// ---------------------------------------------------------------------------
// pool item: one (b,c) plane — avg-pool 8x8 into g_y + fp16 windowed repack.
// Repack (u64 units): g_xpack[bc*16384 + ig*4096 + nh*2048 + k*32
//                             + (il&3)*8 + jc/4],  nh = il>>2, k = mr*8+mc.
// ---------------------------------------------------------------------------
__device__ void do_pool(char* sm, const float* __restrict__ x, int bc) {
    const float* plane = x + (size_t)bc * PLANE;
    int t = threadIdx.x;
    int warp = t >> 5, lane = t & 31;
    float* wsum = (float*)sm;

    if (t < 64) wsum[t] = 0.f;
    __syncthreads();

    int mc1 = lane >> 3;
    int jq  = lane & 7;
    int nh  = warp >> 2;
    int il4 = warp & 3;
    unsigned long long* xp = g_xpack + (size_t)bc * 16384 + nh * 2048 + il4 * 8 + jq;

    for (int pass = 0; pass < 32; pass++) {
        int row = pass * 8 + warp;
        int mr = pass >> 2, ig = pass & 3;
        const float4* rp = (const float4*)(plane + row * IMG);
        float4 v1 = rp[lane];
        float4 v2 = rp[lane + 32];

        {
            __half2 a0 = __floats2half2_rn(v1.x, v1.y);
            __half2 a1 = __floats2half2_rn(v1.z, v1.w);
            __half2 b0 = __floats2half2_rn(v2.x, v2.y);
            __half2 b1 = __floats2half2_rn(v2.z, v2.w);
            unsigned long long u1 = ((unsigned long long)*(uint32_t*)&a1 << 32) | *(uint32_t*)&a0;
            unsigned long long u2 = ((unsigned long long)*(uint32_t*)&b1 << 32) | *(uint32_t*)&b0;
            xp[ig * 4096 + (mr * 8 + mc1) * 32]       = u1;
            xp[ig * 4096 + (mr * 8 + mc1 + 4) * 32]   = u2;
        }

        float s1 = v1.x + v1.y + v1.z + v1.w;
        float s2 = v2.x + v2.y + v2.z + v2.w;
        s1 += __shfl_xor_sync(~0u, s1, 4);
        s1 += __shfl_xor_sync(~0u, s1, 2);
        s1 += __shfl_xor_sync(~0u, s1, 1);
        s2 += __shfl_xor_sync(~0u, s2, 4);
        s2 += __shfl_xor_sync(~0u, s2, 2);
        s2 += __shfl_xor_sync(~0u, s2, 1);
        if ((lane & 7) == 0) {
            int wr = row >> 5;
            atomicAdd(&wsum[wr * 8 + (lane >> 3)], s1);
            atomicAdd(&wsum[wr * 8 + (lane >> 3) + 4], s2);
        }
    }
    __syncthreads();
    if (t < 64) {
        int b = bc >> 6, c = bc & 63;
        g_y[((size_t)b * 64 + t) * NC + c] = wsum[t] * (1.0f / 1024.0f);
    }
}

// ---------------------------------------------------------------------------
// dist item: one batch — q/k projections, softmax, fp16 A image to g_Apack.
// ---------------------------------------------------------------------------
__device__ void do_dist(char* sm, const float* __restrict__ Wq,
                        const float* __restrict__ Wk, int b) {
    float* sY  = (float*)sm;
    float* sA  = (float*)(sm + 16384);
    float* sB2 = (float*)(sm + 32768);
    int t = threadIdx.x;

    for (int idx = t; idx < 4096; idx += 256) {
        sY[idx]  = g_y[b * 4096 + idx];
        sA[idx]  = Wq[idx];
        sB2[idx] = Wk[idx];
    }
    __syncthreads();

    int n = t >> 2;
    int kk = (t & 3) * 16;

    float qv[16], kv[16];
    #pragma unroll
    for (int e = 0; e < 16; e++) {
        float aq = 0.f, ak = 0.f;
        const float* yr = &sY[n * 64];
        const float* wq = &sA[(kk + e) * 64];
        const float* wk = &sB2[(kk + e) * 64];
        #pragma unroll
        for (int c = 0; c < 64; c++) {
            aq = fmaf(yr[c], wq[c], aq);
            ak = fmaf(yr[c], wk[c], ak);
        }
        qv[e] = aq; kv[e] = ak;
    }
    __syncthreads();
    #pragma unroll
    for (int e = 0; e < 16; e++) {
        sA[n * 64 + kk + e]  = qv[e];
        sB2[n * 64 + kk + e] = kv[e];
    }
    __syncthreads();

    float sv[16];
    #pragma unroll
    for (int e = 0; e < 16; e++) {
        int m = kk + e;
        float s = 0.f;
        const float* qr = &sA[n * 64];
        const float* kr = &sB2[m * 64];
        #pragma unroll
        for (int k = 0; k < 64; k++) s = fmaf(qr[k], kr[k], s);
        sv[e] = s * 0.125f;
    }
    __syncthreads();
    #pragma unroll
    for (int e = 0; e < 16; e++) sY[n * 64 + kk + e] = sv[e];
    __syncthreads();

    int warp = t >> 5, lane = t & 31;
    unsigned char* ap = g_Apack + b * 9216;
    for (int j = 0; j < 8; j++) {
        int row = warp * 8 + j;
        float2 v = *(const float2*)&sY[row * 64 + 2 * lane];
        float mx = fmaxf(v.x, v.y);
        for (int d = 16; d >= 1; d >>= 1) mx = fmaxf(mx, __shfl_xor_sync(~0u, mx, d));
        float e0 = expf(v.x - mx), e1 = expf(v.y - mx);
        float s = e0 + e1;
        for (int d = 16; d >= 1; d >>= 1) s += __shfl_xor_sync(~0u, s, d);
        float inv = 1.0f / s;
        __half2 h = __floats2half2_rn(e0 * inv, e1 * inv);
        *(uint32_t*)(ap + row * 144 + lane * 4) = *(uint32_t*)&h;
    }
}

// ---------------------------------------------------------------------------
// att item: one (b,c,ig) tile pair — fp16 HMMA GEMM, 2-tile cp.async pipeline.
// ---------------------------------------------------------------------------
#define SM_A  0            // 9216 B, 144B rows
#define SM_B0 9216         // 64 rows * 272B = 17408
#define SM_B1 26624

__device__ void do_att(char* sm, uint32_t sbase, float* __restrict__ out, int blk) {
    int t = threadIdx.x;
    int wid = t >> 5, lane = t & 31;
    int wm = wid >> 2, wn = wid & 3;

    int ig = blk & 3;
    int c  = (blk >> 2) & 63;
    int b  = blk >> 8;

    const char* gB = (const char*)g_xpack + (size_t)blk * 32768;

    // group 0: A image + B tile 0
    {
        const char* gA = (const char*)g_Apack + b * 9216;
        #pragma unroll
        for (int idx = t; idx < 576; idx += 256) {
            uint32_t d = sbase + SM_A + idx * 16;
            asm volatile("cp.async.cg.shared.global [%0], [%1], 16;"
                         :: "r"(d), "l"(gA + idx * 16));
        }
        #pragma unroll
        for (int idx = t; idx < 1024; idx += 256) {
            int row = idx >> 4, ch = idx & 15;
            uint32_t d = sbase + SM_B0 + row * 272 + ch * 16;
            asm volatile("cp.async.cg.shared.global [%0], [%1], 16;"
                         :: "r"(d), "l"(gB + row * 256 + ch * 16));
        }
        asm volatile("cp.async.commit_group;");
    }

    int row16 = lane & 15;
    uint32_t aH = sbase + SM_A + (uint32_t)(wm * 32 + row16) * 144u + (uint32_t)(lane >> 4) * 16u;
    uint32_t bX4 = (uint32_t)row16 * 272u + (uint32_t)(wn * 64) + (uint32_t)((lane >> 4) * 16);
    float* oplane = out + (size_t)(b * 64 + c) * PLANE;

    #pragma unroll
    for (int i = 0; i < 2; i++) {
        if (i == 0) {
            const char* src = gB + 16384;
            #pragma unroll
            for (int idx = t; idx < 1024; idx += 256) {
                int row = idx >> 4, ch = idx & 15;
                asm volatile("cp.async.cg.shared.global [%0], [%1], 16;"
                             :: "r"(sbase + SM_B1 + row * 272 + ch * 16),
                                "l"(src + row * 256 + ch * 16));
            }
            asm volatile("cp.async.commit_group;");
            asm volatile("cp.async.wait_group 1;" ::: "memory");
        } else {
            asm volatile("cp.async.wait_group 0;" ::: "memory");
        }
        __syncthreads();

        float acc[2][4][4];
        #pragma unroll
        for (int mt = 0; mt < 2; mt++)
            #pragma unroll
            for (int nt = 0; nt < 4; nt++) {
                acc[mt][nt][0] = 0.f; acc[mt][nt][1] = 0.f;
                acc[mt][nt][2] = 0.f; acc[mt][nt][3] = 0.f;
            }
        uint32_t bB = (i ? sbase + SM_B1 : sbase + SM_B0) + bX4;

        #pragma unroll
        for (int kk = 0; kk < 4; kk++) {
            uint32_t bh[4][2];
            #pragma unroll
            for (int np = 0; np < 2; np++) {
                uint32_t addr = bB + (uint32_t)(kk * 16) * 272u + (uint32_t)(np * 32);
                asm volatile("ldmatrix.sync.aligned.m8n8.x4.trans.shared.b16 {%0,%1,%2,%3}, [%4];"
                             : "=r"(bh[2*np][0]), "=r"(bh[2*np][1]),
                               "=r"(bh[2*np+1][0]), "=r"(bh[2*np+1][1])
                             : "r"(addr));
            }
            #pragma unroll
            for (int mt = 0; mt < 2; mt++) {
                uint32_t af[4];
                uint32_t addr = aH + (uint32_t)(mt * 16) * 144u + (uint32_t)(kk * 32);
                asm volatile("ldmatrix.sync.aligned.m8n8.x4.shared.b16 {%0,%1,%2,%3}, [%4];"
                             : "=r"(af[0]), "=r"(af[1]), "=r"(af[2]), "=r"(af[3]) : "r"(addr));
                #pragma unroll
                for (int nt = 0; nt < 4; nt++)
                    asm volatile(
                        "mma.sync.aligned.m16n8k16.row.col.f32.f16.f16.f32 "
                        "{%0,%1,%2,%3}, {%4,%5,%6,%7}, {%8,%9}, {%0,%1,%2,%3};"
                        : "+f"(acc[mt][nt][0]), "+f"(acc[mt][nt][1]),
                          "+f"(acc[mt][nt][2]), "+f"(acc[mt][nt][3])
                        : "r"(af[0]), "r"(af[1]), "r"(af[2]), "r"(af[3]),
                          "r"(bh[nt][0]), "r"(bh[nt][1]));
            }
        }

        {
            int g = lane >> 2, tig = lane & 3;
            int rowbase = ig * 8 + i * 4 + wn;
            #pragma unroll
            for (int mt = 0; mt < 2; mt++) {
                #pragma unroll
                for (int nt = 0; nt < 4; nt++) {
                    int jc = nt * 8 + tig * 2;
                    int n1 = wm * 32 + mt * 16 + g;
                    int n2 = n1 + 8;
                    float* p1 = oplane + (size_t)((n1 >> 3) * 32 + rowbase) * IMG
                              + (n1 & 7) * 32 + jc;
                    float* p2 = oplane + (size_t)((n2 >> 3) * 32 + rowbase) * IMG
                              + (n2 & 7) * 32 + jc;
                    *(float2*)p1 = make_float2(acc[mt][nt][0], acc[mt][nt][1]);
                    *(float2*)p2 = make_float2(acc[mt][nt][2], acc[mt][nt][3]);
                }
            }
        }
    }
}

// ---------------------------------------------------------------------------
// Fused persistent kernel: static-stride work queue over 5136 items.
// Order: [pool b0][pool b1, dist b0, att b0]...[pool b15, dist b14, att b14]
//        [dist b15, att b15]  — pool runs one batch ahead of att (overlap).
// ---------------------------------------------------------------------------
__global__ void __launch_bounds__(256, 3) fused_kernel(const float* __restrict__ x,
                                                       const float* __restrict__ Wq,
                                                       const float* __restrict__ Wk,
                                                       float* __restrict__ out) {
    extern __shared__ char sm[];
    uint32_t sbase = smem_u32(sm);

    for (int p = blockIdx.x; p < N_ITEMS; p += gridDim.x) {
        int type, arg;
        if (p < 64) { type = 0; arg = p; }
        else {
            int q = p - 64;
            int chunk = q / 321;
            if (chunk < 15) {
                int r = q - chunk * 321;
                if (r < 64)       { type = 0; arg = (chunk + 1) * 64 + r; }
                else if (r == 64) { type = 1; arg = chunk; }
                else              { type = 2; arg = chunk * 256 + (r - 65); }
            } else {
                int r2 = q - 4815;
                if (r2 == 0) { type = 1; arg = 15; }
                else         { type = 2; arg = 3840 + (r2 - 1); }
            }
        }

        if (type == 0) {
            do_pool(sm, x, arg);
            __threadfence();
            __syncthreads();
            if (threadIdx.x == 0) atomicAdd(&g_pool_done[arg >> 6], 1u);
        } else if (type == 1) {
            wait_flag(&g_pool_done[arg], 64u);
            do_dist(sm, Wq, Wk, arg);
            __threadfence();
            __syncthreads();
            if (threadIdx.x == 0) atomicAdd(&g_dist_done[arg], 1u);
        } else {
            int b = arg >> 8;
            wait_flag(&g_dist_done[b], 1u);
            do_att(sm, sbase, out, arg);
            __syncthreads();
            if (threadIdx.x == 0) {
                unsigned old = atomicAdd(&g_att_done[b], 1u);
                if (old == 255u) {   // last att item of batch b: reset flags for next run
                    atomicExch(&g_pool_done[b], 0u);
                    atomicExch(&g_dist_done[b], 0u);
                    atomicExch(&g_att_done[b], 0u);
                }
            }
        }
        __syncthreads();   // smem reuse safety between items
    }
}

extern "C" void kernel_launch(void* const* d_in, const int* in_sizes, int n_in,
                              void* d_out, int out_size) {
    const float* x  = (const float*)d_in[0];
    const float* Wq = (const float*)d_in[1];
    const float* Wk = (const float*)d_in[2];
    float* out = (float*)d_out;

    cudaFuncSetAttribute(fused_kernel, cudaFuncAttributeMaxDynamicSharedMemorySize, SMEM_FUSED);

    int sms = 0;
    cudaDeviceGetAttribute(&sms, cudaDevAttrMultiProcessorCount, 0);
    int occ = 0;
    cudaOccupancyMaxActiveBlocksPerMultiprocessor(&occ, fused_kernel, 256, SMEM_FUSED);
    if (occ < 1) occ = 1;
    int grid = sms * occ;               // exactly the resident capacity (spin-safe)
    if (grid > N_ITEMS) grid = N_ITEMS;

    fused_kernel<<<grid, 256, SMEM_FUSED>>>(x, Wq, Wk, out);
}

// round 17
// speedup vs baseline: 1.0281x; 1.0281x over previous
#include <cuda_runtime.h>
#include <cuda_fp16.h>
#include <cstdint>
#include <math.h>

#define NB 16
#define NC 64
#define IMG 256
#define PLANE 65536

// scratch (device globals — no allocation allowed)
__device__ float g_y[NB * 64 * NC];                 // [b][n][c] pooled tokens
__device__ unsigned long long g_xpack[16777216];    // x fp16: [bc][ig][nh][k=64][px=128] (134MB)
__device__ __align__(16) unsigned char g_Apack[NB * 9216]; // dist fp16, 64 rows x 144B

// scheduler state (reset by reset_kernel at the head of every replay)
__device__ unsigned g_next;
__device__ unsigned g_pool_done[NB];
__device__ unsigned g_dist_done[NB];

#define N_ITEMS 5136   // 64 pool(b0) + 15*(64 pool + 1 dist + 256 att) + (1 dist + 256 att)
#define SMEM_FUSED 49152

__global__ void reset_kernel() {
    g_next = 0u;
    for (int b = 0; b < NB; b++) { g_pool_done[b] = 0u; g_dist_done[b] = 0u; }
}

__device__ __forceinline__ uint32_t smem_u32(const void* p) {
    uint32_t a;
    asm("{ .reg .u64 t; cvta.to.shared.u64 t, %1; cvt.u32.u64 %0, t; }"
        : "=r"(a) : "l"(p));
    return a;
}

__device__ __forceinline__ void wait_flag(unsigned* f, unsigned target) {
    if (threadIdx.x == 0) {
        while (atomicAdd(f, 0u) < target) __nanosleep(64);
        __threadfence();
    }
    __syncthreads();
}

// ---------------------------------------------------------------------------
// pool item: one (b,c) plane — avg-pool 8x8 into g_y + fp16 windowed repack.
// ---------------------------------------------------------------------------
__device__ void do_pool(char* sm, const float* __restrict__ x, int bc) {
    const float* plane = x + (size_t)bc * PLANE;
    int t = threadIdx.x;
    int warp = t >> 5, lane = t & 31;
    float* wsum = (float*)sm;

    if (t < 64) wsum[t] = 0.f;
    __syncthreads();

    int mc1 = lane >> 3;
    int jq  = lane & 7;
    int nh  = warp >> 2;
    int il4 = warp & 3;
    unsigned long long* xp = g_xpack + (size_t)bc * 16384 + nh * 2048 + il4 * 8 + jq;

    for (int pass = 0; pass < 32; pass++) {
        int row = pass * 8 + warp;
        int mr = pass >> 2, ig = pass & 3;
        const float4* rp = (const float4*)(plane + row * IMG);
        float4 v1 = rp[lane];
        float4 v2 = rp[lane + 32];

        {
            __half2 a0 = __floats2half2_rn(v1.x, v1.y);
            __half2 a1 = __floats2half2_rn(v1.z, v1.w);
            __half2 b0 = __floats2half2_rn(v2.x, v2.y);
            __half2 b1 = __floats2half2_rn(v2.z, v2.w);
            unsigned long long u1 = ((unsigned long long)*(uint32_t*)&a1 << 32) | *(uint32_t*)&a0;
            unsigned long long u2 = ((unsigned long long)*(uint32_t*)&b1 << 32) | *(uint32_t*)&b0;
            xp[ig * 4096 + (mr * 8 + mc1) * 32]       = u1;
            xp[ig * 4096 + (mr * 8 + mc1 + 4) * 32]   = u2;
        }

        float s1 = v1.x + v1.y + v1.z + v1.w;
        float s2 = v2.x + v2.y + v2.z + v2.w;
        s1 += __shfl_xor_sync(~0u, s1, 4);
        s1 += __shfl_xor_sync(~0u, s1, 2);
        s1 += __shfl_xor_sync(~0u, s1, 1);
        s2 += __shfl_xor_sync(~0u, s2, 4);
        s2 += __shfl_xor_sync(~0u, s2, 2);
        s2 += __shfl_xor_sync(~0u, s2, 1);
        if ((lane & 7) == 0) {
            int wr = row >> 5;
            atomicAdd(&wsum[wr * 8 + (lane >> 3)], s1);
            atomicAdd(&wsum[wr * 8 + (lane >> 3) + 4], s2);
        }
    }
    __syncthreads();
    if (t < 64) {
        int b = bc >> 6, c = bc & 63;
        g_y[((size_t)b * 64 + t) * NC + c] = wsum[t] * (1.0f / 1024.0f);
    }
}

// ---------------------------------------------------------------------------
// dist item: one batch — q/k projections, softmax, fp16 A image to g_Apack.
// ---------------------------------------------------------------------------
__device__ void do_dist(char* sm, const float* __restrict__ Wq,
                        const float* __restrict__ Wk, int b) {
    float* sY  = (float*)sm;
    float* sA  = (float*)(sm + 16384);
    float* sB2 = (float*)(sm + 32768);
    int t = threadIdx.x;

    for (int idx = t; idx < 4096; idx += 256) {
        sY[idx]  = g_y[b * 4096 + idx];
        sA[idx]  = Wq[idx];
        sB2[idx] = Wk[idx];
    }
    __syncthreads();

    int n = t >> 2;
    int kk = (t & 3) * 16;

    float qv[16], kv[16];
    #pragma unroll
    for (int e = 0; e < 16; e++) {
        float aq = 0.f, ak = 0.f;
        const float* yr = &sY[n * 64];
        const float* wq = &sA[(kk + e) * 64];
        const float* wk = &sB2[(kk + e) * 64];
        #pragma unroll
        for (int c = 0; c < 64; c++) {
            aq = fmaf(yr[c], wq[c], aq);
            ak = fmaf(yr[c], wk[c], ak);
        }
        qv[e] = aq; kv[e] = ak;
    }
    __syncthreads();
    #pragma unroll
    for (int e = 0; e < 16; e++) {
        sA[n * 64 + kk + e]  = qv[e];
        sB2[n * 64 + kk + e] = kv[e];
    }
    __syncthreads();

    float sv[16];
    #pragma unroll
    for (int e = 0; e < 16; e++) {
        int m = kk + e;
        float s = 0.f;
        const float* qr = &sA[n * 64];
        const float* kr = &sB2[m * 64];
        #pragma unroll
        for (int k = 0; k < 64; k++) s = fmaf(qr[k], kr[k], s);
        sv[e] = s * 0.125f;
    }
    __syncthreads();
    #pragma unroll
    for (int e = 0; e < 16; e++) sY[n * 64 + kk + e] = sv[e];
    __syncthreads();

    int warp = t >> 5, lane = t & 31;
    unsigned char* ap = g_Apack + b * 9216;
    for (int j = 0; j < 8; j++) {
        int row = warp * 8 + j;
        float2 v = *(const float2*)&sY[row * 64 + 2 * lane];
        float mx = fmaxf(v.x, v.y);
        for (int d = 16; d >= 1; d >>= 1) mx = fmaxf(mx, __shfl_xor_sync(~0u, mx, d));
        float e0 = expf(v.x - mx), e1 = expf(v.y - mx);
        float s = e0 + e1;
        for (int d = 16; d >= 1; d >>= 1) s += __shfl_xor_sync(~0u, s, d);
        float inv = 1.0f / s;
        __half2 h = __floats2half2_rn(e0 * inv, e1 * inv);
        *(uint32_t*)(ap + row * 144 + lane * 4) = *(uint32_t*)&h;
    }
}

// ---------------------------------------------------------------------------
// att item: one (b,c,ig) tile pair — fp16 HMMA GEMM, 2-tile cp.async pipeline.
// ---------------------------------------------------------------------------
#define SM_A  0            // 9216 B, 144B rows
#define SM_B0 9216         // 64 rows * 272B = 17408
#define SM_B1 26624

__device__ void do_att(char* sm, uint32_t sbase, float* __restrict__ out, int blk) {
    int t = threadIdx.x;
    int wid = t >> 5, lane = t & 31;
    int wm = wid >> 2, wn = wid & 3;

    int ig = blk & 3;
    int c  = (blk >> 2) & 63;
    int b  = blk >> 8;

    const char* gB = (const char*)g_xpack + (size_t)blk * 32768;

    {
        const char* gA = (const char*)g_Apack + b * 9216;
        #pragma unroll
        for (int idx = t; idx < 576; idx += 256) {
            uint32_t d = sbase + SM_A + idx * 16;
            asm volatile("cp.async.cg.shared.global [%0], [%1], 16;"
                         :: "r"(d), "l"(gA + idx * 16));
        }
        #pragma unroll
        for (int idx = t; idx < 1024; idx += 256) {
            int row = idx >> 4, ch = idx & 15;
            uint32_t d = sbase + SM_B0 + row * 272 + ch * 16;
            asm volatile("cp.async.cg.shared.global [%0], [%1], 16;"
                         :: "r"(d), "l"(gB + row * 256 + ch * 16));
        }
        asm volatile("cp.async.commit_group;");
    }

    int row16 = lane & 15;
    uint32_t aH = sbase + SM_A + (uint32_t)(wm * 32 + row16) * 144u + (uint32_t)(lane >> 4) * 16u;
    uint32_t bX4 = (uint32_t)row16 * 272u + (uint32_t)(wn * 64) + (uint32_t)((lane >> 4) * 16);
    float* oplane = out + (size_t)(b * 64 + c) * PLANE;

    #pragma unroll
    for (int i = 0; i < 2; i++) {
        if (i == 0) {
            const char* src = gB + 16384;
            #pragma unroll
            for (int idx = t; idx < 1024; idx += 256) {
                int row = idx >> 4, ch = idx & 15;
                asm volatile("cp.async.cg.shared.global [%0], [%1], 16;"
                             :: "r"(sbase + SM_B1 + row * 272 + ch * 16),
                                "l"(src + row * 256 + ch * 16));
            }
            asm volatile("cp.async.commit_group;");
            asm volatile("cp.async.wait_group 1;" ::: "memory");
        } else {
            asm volatile("cp.async.wait_group 0;" ::: "memory");
        }
        __syncthreads();

        float acc[2][4][4];
        #pragma unroll
        for (int mt = 0; mt < 2; mt++)
            #pragma unroll
            for (int nt = 0; nt < 4; nt++) {
                acc[mt][nt][0] = 0.f; acc[mt][nt][1] = 0.f;
                acc[mt][nt][2] = 0.f; acc[mt][nt][3] = 0.f;
            }
        uint32_t bB = (i ? sbase + SM_B1 : sbase + SM_B0) + bX4;

        #pragma unroll
        for (int kk = 0; kk < 4; kk++) {
            uint32_t bh[4][2];
            #pragma unroll
            for (int np = 0; np < 2; np++) {
                uint32_t addr = bB + (uint32_t)(kk * 16) * 272u + (uint32_t)(np * 32);
                asm volatile("ldmatrix.sync.aligned.m8n8.x4.trans.shared.b16 {%0,%1,%2,%3}, [%4];"
                             : "=r"(bh[2*np][0]), "=r"(bh[2*np][1]),
                               "=r"(bh[2*np+1][0]), "=r"(bh[2*np+1][1])
                             : "r"(addr));
            }
            #pragma unroll
            for (int mt = 0; mt < 2; mt++) {
                uint32_t af[4];
                uint32_t addr = aH + (uint32_t)(mt * 16) * 144u + (uint32_t)(kk * 32);
                asm volatile("ldmatrix.sync.aligned.m8n8.x4.shared.b16 {%0,%1,%2,%3}, [%4];"
                             : "=r"(af[0]), "=r"(af[1]), "=r"(af[2]), "=r"(af[3]) : "r"(addr));
                #pragma unroll
                for (int nt = 0; nt < 4; nt++)
                    asm volatile(
                        "mma.sync.aligned.m16n8k16.row.col.f32.f16.f16.f32 "
                        "{%0,%1,%2,%3}, {%4,%5,%6,%7}, {%8,%9}, {%0,%1,%2,%3};"
                        : "+f"(acc[mt][nt][0]), "+f"(acc[mt][nt][1]),
                          "+f"(acc[mt][nt][2]), "+f"(acc[mt][nt][3])
                        : "r"(af[0]), "r"(af[1]), "r"(af[2]), "r"(af[3]),
                          "r"(bh[nt][0]), "r"(bh[nt][1]));
            }
        }

        {
            int g = lane >> 2, tig = lane & 3;
            int rowbase = ig * 8 + i * 4 + wn;
            #pragma unroll
            for (int mt = 0; mt < 2; mt++) {
                #pragma unroll
                for (int nt = 0; nt < 4; nt++) {
                    int jc = nt * 8 + tig * 2;
                    int n1 = wm * 32 + mt * 16 + g;
                    int n2 = n1 + 8;
                    float* p1 = oplane + (size_t)((n1 >> 3) * 32 + rowbase) * IMG
                              + (n1 & 7) * 32 + jc;
                    float* p2 = oplane + (size_t)((n2 >> 3) * 32 + rowbase) * IMG
                              + (n2 & 7) * 32 + jc;
                    *(float2*)p1 = make_float2(acc[mt][nt][0], acc[mt][nt][1]);
                    *(float2*)p2 = make_float2(acc[mt][nt][2], acc[mt][nt][3]);
                }
            }
        }
    }
}

// ---------------------------------------------------------------------------
// Fused persistent kernel, DYNAMIC work queue (atomic ticket; in-order grab).
// Queue: [pool b0][pool b1, dist b0, att b0]...[pool b15, dist b14, att b14]
//        [dist b15, att b15]  — deps always at earlier positions.
// ---------------------------------------------------------------------------
__global__ void __launch_bounds__(256, 3) fused_kernel(const float* __restrict__ x,
                                                       const float* __restrict__ Wq,
                                                       const float* __restrict__ Wk,
                                                       float* __restrict__ out) {
    extern __shared__ char sm[];
    uint32_t sbase = smem_u32(sm);
    __shared__ unsigned s_p;

    for (;;) {
        if (threadIdx.x == 0) s_p = atomicAdd(&g_next, 1u);
        __syncthreads();
        unsigned p = s_p;
        __syncthreads();
        if (p >= N_ITEMS) break;

        int type, arg;
        if (p < 64) { type = 0; arg = (int)p; }
        else {
            int q = (int)p - 64;
            int chunk = q / 321;
            if (chunk < 15) {
                int r = q - chunk * 321;
                if (r < 64)       { type = 0; arg = (chunk + 1) * 64 + r; }
                else if (r == 64) { type = 1; arg = chunk; }
                else              { type = 2; arg = chunk * 256 + (r - 65); }
            } else {
                int r2 = q - 4815;
                if (r2 == 0) { type = 1; arg = 15; }
                else         { type = 2; arg = 3840 + (r2 - 1); }
            }
        }

        if (type == 0) {
            do_pool(sm, x, arg);
            __threadfence();
            __syncthreads();
            if (threadIdx.x == 0) atomicAdd(&g_pool_done[arg >> 6], 1u);
        } else if (type == 1) {
            wait_flag(&g_pool_done[arg], 64u);
            do_dist(sm, Wq, Wk, arg);
            __threadfence();
            __syncthreads();
            if (threadIdx.x == 0) atomicAdd(&g_dist_done[arg], 1u);
        } else {
            wait_flag(&g_dist_done[arg >> 8], 1u);
            do_att(sm, sbase, out, arg);
        }
        __syncthreads();   // smem reuse safety between items
    }
}

extern "C" void kernel_launch(void* const* d_in, const int* in_sizes, int n_in,
                              void* d_out, int out_size) {
    const float* x  = (const float*)d_in[0];
    const float* Wq = (const float*)d_in[1];
    const float* Wk = (const float*)d_in[2];
    float* out = (float*)d_out;

    cudaFuncSetAttribute(fused_kernel, cudaFuncAttributeMaxDynamicSharedMemorySize, SMEM_FUSED);

    int sms = 0;
    cudaDeviceGetAttribute(&sms, cudaDevAttrMultiProcessorCount, 0);
    int occ = 0;
    cudaOccupancyMaxActiveBlocksPerMultiprocessor(&occ, fused_kernel, 256, SMEM_FUSED);
    if (occ < 1) occ = 1;
    int grid = sms * occ;               // exactly the resident capacity (spin-safe)
    if (grid > N_ITEMS) grid = N_ITEMS;

    reset_kernel<<<1, 1>>>();
    fused_kernel<<<grid, 256, SMEM_FUSED>>>(x, Wq, Wk, out);
}